// round 12
// baseline (speedup 1.0000x reference)
#include <cuda_runtime.h>
#include <cstdint>

// Problem constants
#define N_TILES 1024
#define PTS     256
#define IN_F    256
#define OUT_F   256
#define OMEGA   30.0f

#define THREADS 256
#define KC      32
#define NSTAGES 8

// SMEM: A stage = 128 rows x 36 words = 18432 B; B stage = 128 x 34 words = 17408 B
#define A_STRIDE_W 36
#define B_STRIDE_W 34
#define A_STAGE_B  18432
#define B_STAGE_B  17408
#define B_BASE_B   (2 * A_STAGE_B)                 // 36864
#define SMEM_BYTES (B_BASE_B + 2 * B_STAGE_B)      // 71680

__device__ int g_idx[N_TILES];

// ---------------------------------------------------------------------------
// Index decode: int32 or int64 input (values < 1024 -> high words zero if i64)
// ---------------------------------------------------------------------------
__global__ void decode_indices_kernel(const void* p) {
    __shared__ int s_not64;
    const int t = threadIdx.x;
    if (t == 0) s_not64 = 0;
    __syncthreads();
    const int* pi = (const int*)p;
    if (t < 512 && pi[2 * t + 1] != 0) s_not64 = 1;
    __syncthreads();
    int v;
    if (s_not64) v = pi[t];
    else         v = (int)((const long long*)p)[t];
    g_idx[t] = v;
}

// ---------------------------------------------------------------------------
__device__ __forceinline__ uint32_t f2tf32(float f) {
    uint32_t r;
    asm("cvt.rna.tf32.f32 %0, %1;" : "=r"(r) : "f"(f));
    return r;
}

__device__ __forceinline__ void mma_tf32(float (&c)[4],
                                         uint32_t a0, uint32_t a1, uint32_t a2, uint32_t a3,
                                         uint32_t b0, uint32_t b1) {
    asm volatile(
        "mma.sync.aligned.m16n8k8.row.col.f32.tf32.tf32.f32 "
        "{%0,%1,%2,%3}, {%4,%5,%6,%7}, {%8,%9}, {%0,%1,%2,%3};"
        : "+f"(c[0]), "+f"(c[1]), "+f"(c[2]), "+f"(c[3])
        : "r"(a0), "r"(a1), "r"(a2), "r"(a3), "r"(b0), "r"(b1));
}

// Fast sine: q = round(x/pi); r = x - q*pi; sin(x) = (-1)^q * poly(r).
__device__ __forceinline__ float fast_sin(float x) {
    float t = x * 0.3183098861837907f;
    int   q = __float2int_rn(t);
    float fq = __int2float_rn(q);
    float r = fmaf(fq, -3.14159274101257f, x);
    r = fmaf(fq, 8.742277657347586e-8f, r);
    float r2 = r * r;
    float p = fmaf(r2, 2.7525562e-6f, -1.9840874e-4f);
    p = fmaf(r2, p, 8.3333310e-3f);
    p = fmaf(r2, p, -1.6666667e-1f);
    p = fmaf(r2 * r, p, r);
    return __int_as_float(__float_as_int(p) ^ (q << 31));
}

// ---------------------------------------------------------------------------
// HMMA v2: fragment-order SMEM, producer-side tf32 rounding (rna, once).
// grid = (4, 1024): quadrant fastest (tile's 4 CTAs co-resident -> L2 reuse).
// CTA: 128x128 tile, K=256; 8 warps 2(M)x4(N); warp tile 64x32; mma m16n8k8.
//
// A smem: row m (0..127), stride 36 words. k decomposed k = 8*kki + 4*h + j:
//   word = m*36 + ((j+m)&3)*8 + h*4 + kki      (slot-swizzled, 16B aligned)
//   consumer thread (rl,ln4): 8 contiguous words at slot (ln4+m)&3 -> 2xLDS.128
// B smem: row n (0..127), stride 34 words:
//   word = n*34 + ((j+(n>>4))&3)*8 + h*4 + kki (8B aligned -> 4xLDS.64 per n)
// Both consumer patterns verified bank-conflict-free per phase.
// ---------------------------------------------------------------------------
extern "C" __global__ void __launch_bounds__(THREADS, 2)
adaptive_sin_v2(const float* __restrict__ x, const float* __restrict__ weight,
                const float* __restrict__ bias, float* __restrict__ out) {
    extern __shared__ uint32_t smw[];

    const int tid  = threadIdx.x;
    const int lane = tid & 31;
    const int wid  = tid >> 5;
    const int wm   = wid >> 2;        // 0..1
    const int wn   = wid & 3;         // 0..3
    const int rl   = lane >> 2;       // groupID 0..7
    const int ln4  = lane & 3;        // threadID_in_group

    const int t    = blockIdx.y;
    const int quad = blockIdx.x;
    const int m_base = (quad & 1) * 128;
    const int n_base = (quad >> 1) * 128;

    const int ch = g_idx[t];
    const float* gA = x + ((size_t)t * PTS + m_base) * IN_F;
    const float* gB = weight + (size_t)ch * (IN_F * OUT_F) + n_base;

    float acc[4][4][4];
#pragma unroll
    for (int i = 0; i < 4; i++)
#pragma unroll
        for (int j = 0; j < 4; j++)
#pragma unroll
            for (int k = 0; k < 4; k++) acc[i][j][k] = 0.f;

    // ---- producer: LDG -> cvt.rna.tf32 (once) -> STS in fragment order ----
    auto produce = [&](uint32_t* As, uint32_t* Bs, int k0) {
        // A: 4 x LDG.128, each float4 = 4 consecutive k at one row
        float4 av[4];
#pragma unroll
        for (int i = 0; i < 4; i++) {
            int id = tid + i * 256;
            int row = id >> 3, c8 = id & 7;
            av[i] = *(const float4*)(gA + (size_t)row * IN_F + k0 + c8 * 4);
        }
        // B: 16 x LDG.32, 4 k at one n per i (coalesced along n per warp)
        const int n  = tid & 127;
        const int hi = tid >> 7;
        const int nt = n >> 4;
        float bvv[4][4];
#pragma unroll
        for (int i = 0; i < 4; i++) {
            int q = 2 * i + hi;
#pragma unroll
            for (int j = 0; j < 4; j++)
                bvv[i][j] = __ldg(gB + (size_t)(k0 + 4 * q + j) * OUT_F + n);
        }
        // stores
#pragma unroll
        for (int i = 0; i < 4; i++) {
            int id = tid + i * 256;
            int row = id >> 3, c8 = id & 7;
            int w = (c8 & 1) * 4 + (c8 >> 1);
            uint32_t* base = As + row * A_STRIDE_W + w;
            base[(((0 + row) & 3) << 3)] = f2tf32(av[i].x);
            base[(((1 + row) & 3) << 3)] = f2tf32(av[i].y);
            base[(((2 + row) & 3) << 3)] = f2tf32(av[i].z);
            base[(((3 + row) & 3) << 3)] = f2tf32(av[i].w);
        }
#pragma unroll
        for (int i = 0; i < 4; i++) {
            int q = 2 * i + hi;
            int w = (q & 1) * 4 + (q >> 1);
            uint32_t* base = Bs + n * B_STRIDE_W + w;
            base[(((0 + nt) & 3) << 3)] = f2tf32(bvv[i][0]);
            base[(((1 + nt) & 3) << 3)] = f2tf32(bvv[i][1]);
            base[(((2 + nt) & 3) << 3)] = f2tf32(bvv[i][2]);
            base[(((3 + nt) & 3) << 3)] = f2tf32(bvv[i][3]);
        }
    };

    produce(smw, smw + B_BASE_B / 4, 0);
    __syncthreads();

#pragma unroll 2
    for (int s = 0; s < NSTAGES; s++) {
        uint32_t* As = smw + (s & 1) * (A_STAGE_B / 4);
        uint32_t* Bs = smw + B_BASE_B / 4 + (s & 1) * (B_STAGE_B / 4);

        // ---- consume: B fragments (16 x LDS.64), then per-sm A + MMA ----
        uint32_t bfr[4][8];
#pragma unroll
        for (int sn = 0; sn < 4; sn++) {
            int n = wn * 32 + sn * 8 + rl;                 // B col = groupID
            int sl = (ln4 + (n >> 4)) & 3;
            const uint32_t* p = Bs + n * B_STRIDE_W + sl * 8;
            *(uint2*)&bfr[sn][0] = *(const uint2*)(p + 0);
            *(uint2*)&bfr[sn][2] = *(const uint2*)(p + 2);
            *(uint2*)&bfr[sn][4] = *(const uint2*)(p + 4);
            *(uint2*)&bfr[sn][6] = *(const uint2*)(p + 6);
        }
#pragma unroll
        for (int sm = 0; sm < 4; sm++) {
            int m  = wm * 64 + sm * 16 + rl;
            int sl = (ln4 + m) & 3;
            const uint32_t* p0 = As + m * A_STRIDE_W + sl * 8;
            const uint32_t* p1 = p0 + 8 * A_STRIDE_W;      // row m+8, same slot
            uint32_t ar0[8], ar1[8];
            *(uint4*)&ar0[0] = *(const uint4*)(p0);
            *(uint4*)&ar0[4] = *(const uint4*)(p0 + 4);
            *(uint4*)&ar1[0] = *(const uint4*)(p1);
            *(uint4*)&ar1[4] = *(const uint4*)(p1 + 4);
#pragma unroll
            for (int kki = 0; kki < 4; kki++)
#pragma unroll
                for (int sn = 0; sn < 4; sn++)
                    mma_tf32(acc[sm][sn],
                             ar0[kki], ar1[kki], ar0[4 + kki], ar1[4 + kki],
                             bfr[sn][kki], bfr[sn][4 + kki]);
        }

        if (s < NSTAGES - 1) {
            uint32_t* Anx = smw + ((s + 1) & 1) * (A_STAGE_B / 4);
            uint32_t* Bnx = smw + B_BASE_B / 4 + ((s + 1) & 1) * (B_STAGE_B / 4);
            produce(Anx, Bnx, (s + 1) * KC);
        }
        __syncthreads();
    }

    // ---- epilogue: bias + sin(OMEGA*z), streaming float2 stores (as R4) ----
    float2 bv[4];
#pragma unroll
    for (int sn = 0; sn < 4; sn++) {
        int n0 = n_base + wn * 32 + sn * 8 + 2 * ln4;
        bv[sn] = *(const float2*)(bias + n0);
    }

#pragma unroll
    for (int sm = 0; sm < 4; sm++) {
        const int r0 = m_base + wm * 64 + sm * 16 + rl;
#pragma unroll
        for (int sn = 0; sn < 4; sn++) {
            const int c0 = n_base + wn * 32 + sn * 8 + 2 * ln4;
            float* o0 = out + ((size_t)t * PTS + r0) * OUT_F + c0;
            float* o1 = o0 + 8 * OUT_F;
            float2 v0, v1;
            v0.x = fast_sin(OMEGA * (acc[sm][sn][0] + bv[sn].x));
            v0.y = fast_sin(OMEGA * (acc[sm][sn][1] + bv[sn].y));
            v1.x = fast_sin(OMEGA * (acc[sm][sn][2] + bv[sn].x));
            v1.y = fast_sin(OMEGA * (acc[sm][sn][3] + bv[sn].y));
            __stcs((float2*)o0, v0);
            __stcs((float2*)o1, v1);
        }
    }
}

// ---------------------------------------------------------------------------
extern "C" void kernel_launch(void* const* d_in, const int* in_sizes, int n_in,
                              void* d_out, int out_size) {
    const float* x      = (const float*)d_in[0];
    const float* weight = (const float*)d_in[1];
    const float* bias   = (const float*)d_in[2];
    const void*  indices = d_in[3];
    float* out = (float*)d_out;

    cudaFuncSetAttribute(adaptive_sin_v2,
                         cudaFuncAttributeMaxDynamicSharedMemorySize,
                         SMEM_BYTES);

    decode_indices_kernel<<<1, N_TILES>>>(indices);

    dim3 grid(4, N_TILES);   // quadrant fastest -> tile's 4 CTAs co-resident in L2
    adaptive_sin_v2<<<grid, THREADS, SMEM_BYTES>>>(x, weight, bias, out);
}

// round 17
// speedup vs baseline: 1.1620x; 1.1620x over previous
#include <cuda_runtime.h>
#include <cstdint>

// Problem constants
#define N_TILES 1024
#define PTS     256
#define IN_F    256
#define OUT_F   256
#define OMEGA   30.0f

// Tiling (identical to the 254.6us R4 kernel)
#define BM 128
#define BN 128
#define KC 32
#define NSTAGES (IN_F / KC)    // 8
#define THREADS 256

#define A_BUF_BYTES (BM * KC * 4)          // 16KB
#define B_BUF_BYTES (KC * BN * 4)          // 16KB
#define SMEM_BYTES  (2 * (A_BUF_BYTES + B_BUF_BYTES))   // 64KB
#define B_BASE_OFF  (2 * A_BUF_BYTES)

__device__ int g_idx[N_TILES];

// ---------------------------------------------------------------------------
// Index decode: int32 or int64 input (values < 1024 -> high words zero if i64)
// ---------------------------------------------------------------------------
__global__ void decode_indices_kernel(const void* p) {
    __shared__ int s_not64;
    const int t = threadIdx.x;
    if (t == 0) s_not64 = 0;
    __syncthreads();
    const int* pi = (const int*)p;
    if (t < 512 && pi[2 * t + 1] != 0) s_not64 = 1;
    __syncthreads();
    int v;
    if (s_not64) v = pi[t];
    else         v = (int)((const long long*)p)[t];
    g_idx[t] = v;
}

// ---------------------------------------------------------------------------
__device__ __forceinline__ uint32_t f2tf32(float f) {
    uint32_t r;
    asm("cvt.rna.tf32.f32 %0, %1;" : "=r"(r) : "f"(f));
    return r;
}

__device__ __forceinline__ void mma_tf32(float (&c)[4], const uint32_t (&a)[4],
                                         const uint32_t (&b)[2]) {
    asm volatile(
        "mma.sync.aligned.m16n8k8.row.col.f32.tf32.tf32.f32 "
        "{%0,%1,%2,%3}, {%4,%5,%6,%7}, {%8,%9}, {%0,%1,%2,%3};"
        : "+f"(c[0]), "+f"(c[1]), "+f"(c[2]), "+f"(c[3])
        : "r"(a[0]), "r"(a[1]), "r"(a[2]), "r"(a[3]),
          "r"(b[0]), "r"(b[1]));
}

// Fast sine: q = round(x/pi); r = x - q*pi; sin(x) = (-1)^q * poly(r).
__device__ __forceinline__ float fast_sin(float x) {
    float t = x * 0.3183098861837907f;
    int   q = __float2int_rn(t);
    float fq = __int2float_rn(q);
    float r = fmaf(fq, -3.14159274101257f, x);
    r = fmaf(fq, 8.742277657347586e-8f, r);
    float r2 = r * r;
    float p = fmaf(r2, 2.7525562e-6f, -1.9840874e-4f);
    p = fmaf(r2, p, 8.3333310e-3f);
    p = fmaf(r2, p, -1.6666667e-1f);
    p = fmaf(r2 * r, p, r);
    return __int_as_float(__float_as_int(p) ^ (q << 31));
}

// ---------------------------------------------------------------------------
// v3: R4's proven layout/consumer, producer-side tf32 CVT + STS.128.
// grid = (4, 1024): quadrant fastest -> tile's 4 CTAs co-resident (L2 reuse).
// CTA: 128x128 tile, K=256; 8 warps 2(M)x4(N); warp tile 64x32; mma m16n8k8.
// A smem row m: 8 chunks of 16B, chunk c8 at ((c8 ^ (m&7))<<4)  [R4 swizzle]
// B smem row kr: 32 chunks of 16B, chunk c at ((c ^ ((kr&3)<<1))<<4)
// Consumer LDS patterns identical to R4 (bank-conflict-free), minus the CVTs.
// ---------------------------------------------------------------------------
extern "C" __global__ void __launch_bounds__(THREADS, 2)
adaptive_sin_v3(const float* __restrict__ x, const float* __restrict__ weight,
                const float* __restrict__ bias, float* __restrict__ out) {
    extern __shared__ char smem[];

    const int tid  = threadIdx.x;
    const int lane = tid & 31;
    const int wid  = tid >> 5;
    const int wm   = wid >> 2;        // 0..1
    const int wn   = wid & 3;         // 0..3
    const int rl   = lane >> 2;       // groupID 0..7
    const int ln4  = lane & 3;        // threadID_in_group
    const int l16  = lane >> 4;       // 0..1
    const int q3   = (lane >> 2) & 3;

    const int t    = blockIdx.y;
    const int quad = blockIdx.x;
    const int m_base = (quad & 1) * BM;
    const int n_base = (quad >> 1) * BN;

    const int ch = g_idx[t];
    const float* gA = x + ((size_t)t * PTS + m_base) * IN_F;
    const float* gB = weight + (size_t)ch * (IN_F * OUT_F) + n_base;

    float acc[4][4][4];
#pragma unroll
    for (int i = 0; i < 4; i++)
#pragma unroll
        for (int j = 0; j < 4; j++)
#pragma unroll
            for (int k = 0; k < 4; k++) acc[i][j][k] = 0.f;

    // ---- producer: LDG.128 -> cvt.rna.tf32 x4 -> STS.128 (R4 addresses) ----
    auto produce = [&](int buf, int kt) {
        const int k0 = kt * KC;
        char* aOff = smem + buf * A_BUF_BYTES;
        char* bOff = smem + B_BASE_OFF + buf * B_BUF_BYTES;
        // A: 128 rows x 8 chunks; 4 LDG.128 per thread
        float4 av[4];
#pragma unroll
        for (int i = 0; i < 4; i++) {
            int id = tid + i * THREADS;
            int row = id >> 3, c8 = id & 7;
            av[i] = *(const float4*)(gA + (size_t)row * IN_F + k0 + c8 * 4);
        }
        // B: 32 k-rows x 32 chunks; 4 LDG.128 per thread
        float4 bv[4];
#pragma unroll
        for (int i = 0; i < 4; i++) {
            int id = tid + i * THREADS;
            int kr = id >> 5, c32 = id & 31;
            bv[i] = *(const float4*)(gB + (size_t)(k0 + kr) * OUT_F + c32 * 4);
        }
        // convert + store (vectorized, conflict-free phases)
#pragma unroll
        for (int i = 0; i < 4; i++) {
            int id = tid + i * THREADS;
            int row = id >> 3, c8 = id & 7;
            uint4 w;
            w.x = f2tf32(av[i].x); w.y = f2tf32(av[i].y);
            w.z = f2tf32(av[i].z); w.w = f2tf32(av[i].w);
            *(uint4*)(aOff + row * 128 + ((c8 ^ (row & 7)) << 4)) = w;
        }
#pragma unroll
        for (int i = 0; i < 4; i++) {
            int id = tid + i * THREADS;
            int kr = id >> 5, c32 = id & 31;
            uint4 w;
            w.x = f2tf32(bv[i].x); w.y = f2tf32(bv[i].y);
            w.z = f2tf32(bv[i].z); w.w = f2tf32(bv[i].w);
            *(uint4*)(bOff + kr * 512 + ((c32 ^ ((kr & 3) << 1)) << 4)) = w;
        }
    };

    produce(0, 0);
    __syncthreads();

#pragma unroll 2
    for (int kt = 0; kt < NSTAGES; kt++) {
        const char* A = smem + (kt & 1) * A_BUF_BYTES;
        const char* B = smem + B_BASE_OFF + (kt & 1) * B_BUF_BYTES;

        // ---- consume (R4 structure, values already tf32 -> no CVT) ----
#pragma unroll
        for (int kki = 0; kki < 4; kki++) {
            const int kk = kki * 8;
            uint32_t af[4][4];
#pragma unroll
            for (int sm = 0; sm < 4; sm++) {
                int base = (wm * 64 + sm * 16 + rl) * 128 +
                           (((kk >> 2) ^ rl) << 4) + ln4 * 4;
                af[sm][0] = *(const uint32_t*)(A + base);
                af[sm][1] = *(const uint32_t*)(A + base + 8 * 128);
                af[sm][2] = *(const uint32_t*)(A + (base ^ 16));
                af[sm][3] = *(const uint32_t*)(A + ((base + 8 * 128) ^ 16));
            }
            uint32_t bf[4][2];
#pragma unroll
            for (int sn = 0; sn < 4; sn++) {
                int n0q = wn * 8 + sn * 2;
                int chunk = (n0q + l16) ^ (ln4 << 1);
                int addr = (kk + ln4) * 512 + (chunk << 4) + q3 * 4;
                bf[sn][0] = *(const uint32_t*)(B + addr);
                bf[sn][1] = *(const uint32_t*)(B + addr + 4 * 512);
            }
#pragma unroll
            for (int sm = 0; sm < 4; sm++)
#pragma unroll
                for (int sn = 0; sn < 4; sn++)
                    mma_tf32(acc[sm][sn], af[sm], bf[sn]);
        }

        // ---- produce next stage (no registers held across the MMAs) ----
        if (kt + 1 < NSTAGES)
            produce((kt + 1) & 1, kt + 1);
        __syncthreads();
    }

    // ---- epilogue: bias + sin(OMEGA*z), streaming float2 stores ----
    float2 bv2[4];
#pragma unroll
    for (int sn = 0; sn < 4; sn++) {
        int n0 = n_base + wn * 32 + sn * 8 + 2 * ln4;
        bv2[sn] = *(const float2*)(bias + n0);
    }

#pragma unroll
    for (int sm = 0; sm < 4; sm++) {
        const int r0 = m_base + wm * 64 + sm * 16 + rl;
#pragma unroll
        for (int sn = 0; sn < 4; sn++) {
            const int c0 = n_base + wn * 32 + sn * 8 + 2 * ln4;
            float* o0 = out + ((size_t)t * PTS + r0) * OUT_F + c0;
            float* o1 = o0 + 8 * OUT_F;
            float2 v0, v1;
            v0.x = fast_sin(OMEGA * (acc[sm][sn][0] + bv2[sn].x));
            v0.y = fast_sin(OMEGA * (acc[sm][sn][1] + bv2[sn].y));
            v1.x = fast_sin(OMEGA * (acc[sm][sn][2] + bv2[sn].x));
            v1.y = fast_sin(OMEGA * (acc[sm][sn][3] + bv2[sn].y));
            __stcs((float2*)o0, v0);
            __stcs((float2*)o1, v1);
        }
    }
}

// ---------------------------------------------------------------------------
extern "C" void kernel_launch(void* const* d_in, const int* in_sizes, int n_in,
                              void* d_out, int out_size) {
    const float* x      = (const float*)d_in[0];
    const float* weight = (const float*)d_in[1];
    const float* bias   = (const float*)d_in[2];
    const void*  indices = d_in[3];
    float* out = (float*)d_out;

    cudaFuncSetAttribute(adaptive_sin_v3,
                         cudaFuncAttributeMaxDynamicSharedMemorySize,
                         SMEM_BYTES);

    decode_indices_kernel<<<1, N_TILES>>>(indices);

    dim3 grid(4, N_TILES);   // quadrant fastest -> tile's 4 CTAs co-resident in L2
    adaptive_sin_v3<<<grid, THREADS, SMEM_BYTES>>>(x, weight, bias, out);
}